// round 3
// baseline (speedup 1.0000x reference)
#include <cuda_runtime.h>

#define SEQ   1024
#define HID   512
#define GATES 2048
#define EMB   512
#define G_CTAS 64
#define UNITS_PER 8   // HID / G_CTAS
#define FLAG_STRIDE 32  // 128 B between flags -> distinct L2 lines

// ---------------- device scratch (static, no allocation) ----------------
__device__ float    g_xg[SEQ * GATES];      // 8 MB precomputed input gates (L2-resident)
__device__ float    g_h[2][HID];            // double-buffered hidden state
__device__ unsigned g_flag[G_CTAS * FLAG_STRIDE];  // per-CTA step counters

__device__ __forceinline__ float fsigm(float x) {
    return 1.0f / (1.0f + __expf(-x));
}
__device__ __forceinline__ float ftanh(float x) {
    // tanh(x) = 2*sigmoid(2x)-1 ; __expf is MUFU ex2.approx (~1e-7 rel err)
    return 2.0f / (1.0f + __expf(-2.0f * x)) - 1.0f;
}

// ---------------- init: reset flags + zero h (runs every replay) ------
__global__ void init_kernel() {
    int t = blockIdx.x * blockDim.x + threadIdx.x;
    if (t < 2 * HID) ((float*)g_h)[t] = 0.0f;
    if (t < G_CTAS * FLAG_STRIDE) g_flag[t] = 0u;
}

// ---------------- kernel 1: x_gates = emb[tok] @ w_ih^T + (b_ih+b_hh) ---
__global__ void __launch_bounds__(256) xgates_gemm(
    const int*   __restrict__ tok,
    const float* __restrict__ emb,
    const float* __restrict__ w_ih,
    const float* __restrict__ b_ih,
    const float* __restrict__ b_hh)
{
    __shared__ float As[32][68];
    __shared__ float Bs[32][68];
    __shared__ int   stok[64];

    const int tid = threadIdx.x;
    const int bm = blockIdx.y * 64;   // token base
    const int bn = blockIdx.x * 64;   // gate base

    if (tid < 64) stok[tid] = tok[bm + tid];
    __syncthreads();

    float acc[4][4];
    #pragma unroll
    for (int i = 0; i < 4; i++)
        #pragma unroll
        for (int j = 0; j < 4; j++) acc[i][j] = 0.0f;

    const int tr = tid >> 4;
    const int tc = tid & 15;

    for (int k0 = 0; k0 < EMB; k0 += 32) {
        #pragma unroll
        for (int i = 0; i < 2; i++) {
            int idx = tid + 256 * i;
            int row = idx & 63;
            int k4  = idx >> 6;
            float4 av = *reinterpret_cast<const float4*>(
                emb + (size_t)stok[row] * EMB + k0 + k4 * 4);
            As[k4*4+0][row] = av.x; As[k4*4+1][row] = av.y;
            As[k4*4+2][row] = av.z; As[k4*4+3][row] = av.w;
            float4 bv = *reinterpret_cast<const float4*>(
                w_ih + (size_t)(bn + row) * EMB + k0 + k4 * 4);
            Bs[k4*4+0][row] = bv.x; Bs[k4*4+1][row] = bv.y;
            Bs[k4*4+2][row] = bv.z; Bs[k4*4+3][row] = bv.w;
        }
        __syncthreads();

        #pragma unroll
        for (int kk = 0; kk < 32; kk++) {
            float4 a4 = *reinterpret_cast<const float4*>(&As[kk][tr * 4]);
            float4 b4 = *reinterpret_cast<const float4*>(&Bs[kk][tc * 4]);
            float a[4] = {a4.x, a4.y, a4.z, a4.w};
            float b[4] = {b4.x, b4.y, b4.z, b4.w};
            #pragma unroll
            for (int i = 0; i < 4; i++)
                #pragma unroll
                for (int j = 0; j < 4; j++)
                    acc[i][j] = fmaf(a[i], b[j], acc[i][j]);
        }
        __syncthreads();
    }

    const int gcol = bn + tc * 4;
    float4 bias;
    bias.x = b_ih[gcol + 0] + b_hh[gcol + 0];
    bias.y = b_ih[gcol + 1] + b_hh[gcol + 1];
    bias.z = b_ih[gcol + 2] + b_hh[gcol + 2];
    bias.w = b_ih[gcol + 3] + b_hh[gcol + 3];
    #pragma unroll
    for (int i = 0; i < 4; i++) {
        int trow = bm + tr * 4 + i;
        float4 v;
        v.x = acc[i][0] + bias.x;
        v.y = acc[i][1] + bias.y;
        v.z = acc[i][2] + bias.z;
        v.w = acc[i][3] + bias.w;
        *reinterpret_cast<float4*>(g_xg + (size_t)trow * GATES + gcol) = v;
    }
}

// ---------------- kernel 2: persistent LSTM scan -------------------------
// 64 CTAs x 256 threads. CTA owns 8 hidden units (32 gate rows).
// Point-to-point flag sync (no central barrier): CTA j publishes step t by
// release-storing g_flag[j] = t+1 after writing its h slice. Consumers
// acquire-poll flags >= t before reading h_{t-1}. Buffer-overwrite safety is
// transitive: flag_j >= t implies CTA j finished step t-1, hence already READ
// buf[t&1]; so writing buf[t&1] at step t cannot race any reader.
__global__ void __launch_bounds__(256, 1) lstm_scan(const float* __restrict__ w_hh)
{
    const int tid  = threadIdx.x;
    const int warp = tid >> 5;
    const int lane = tid & 31;
    const int base = blockIdx.x * UNITS_PER;

    // Preload weight slices into registers (persistent across all 1024 steps).
    float w[4][16];
    #pragma unroll
    for (int q = 0; q < 4; q++) {
        int lr   = warp * 4 + q;                       // local row 0..31
        int grow = (lr >> 3) * HID + base + (lr & 7);  // gate*512 + base + unit
        const float4* src =
            reinterpret_cast<const float4*>(w_hh + (size_t)grow * HID) + lane * 4;
        float4 v0 = src[0], v1 = src[1], v2 = src[2], v3 = src[3];
        w[q][0]=v0.x; w[q][1]=v0.y; w[q][2]=v0.z; w[q][3]=v0.w;
        w[q][4]=v1.x; w[q][5]=v1.y; w[q][6]=v1.z; w[q][7]=v1.w;
        w[q][8]=v2.x; w[q][9]=v2.y; w[q][10]=v2.z; w[q][11]=v2.w;
        w[q][12]=v3.x; w[q][13]=v3.y; w[q][14]=v3.z; w[q][15]=v3.w;
    }

    __shared__ float gates_s[32];
    float c_state = 0.0f;

    for (int t = 0; t < SEQ; t++) {
        // xg loads are independent of the scan: issue before the poll so their
        // latency hides behind the spin. L1-cacheable (immutable this launch).
        float xgv0 = 0.f, xgv1 = 0.f, xgv2 = 0.f, xgv3 = 0.f;
        if (tid < 8) {
            const float* xp = g_xg + (size_t)t * GATES + base + tid;
            xgv0 = __ldg(xp);
            xgv1 = __ldg(xp + 512);
            xgv2 = __ldg(xp + 1024);
            xgv3 = __ldg(xp + 1536);
        }

        // Wait for all producers to have published step t-1 (flag >= t).
        if (tid < G_CTAS) {
            const unsigned* fp = g_flag + tid * FLAG_STRIDE;
            unsigned v;
            do {
                asm volatile("ld.global.acquire.gpu.b32 %0, [%1];"
                             : "=r"(v) : "l"(fp) : "memory");
            } while (v < (unsigned)t);
        }
        __syncthreads();   // extends acquire ordering CTA-wide

        // h_{t-1} lives in buf[(t-1)&1] == buf[(t+1)&1]; zeros for t==0.
        const float4* hsrc =
            reinterpret_cast<const float4*>(g_h[(t + 1) & 1]) + lane * 4;
        float4 h0 = __ldcg(hsrc + 0);
        float4 h1 = __ldcg(hsrc + 1);
        float4 h2 = __ldcg(hsrc + 2);
        float4 h3 = __ldcg(hsrc + 3);

        float hv[16] = {h0.x,h0.y,h0.z,h0.w, h1.x,h1.y,h1.z,h1.w,
                        h2.x,h2.y,h2.z,h2.w, h3.x,h3.y,h3.z,h3.w};

        float acc0 = 0.f, acc1 = 0.f, acc2 = 0.f, acc3 = 0.f;
        #pragma unroll
        for (int m = 0; m < 16; m++) {
            float h = hv[m];
            acc0 = fmaf(w[0][m], h, acc0);
            acc1 = fmaf(w[1][m], h, acc1);
            acc2 = fmaf(w[2][m], h, acc2);
            acc3 = fmaf(w[3][m], h, acc3);
        }
        #pragma unroll
        for (int off = 16; off; off >>= 1) {
            acc0 += __shfl_xor_sync(0xffffffffu, acc0, off);
            acc1 += __shfl_xor_sync(0xffffffffu, acc1, off);
            acc2 += __shfl_xor_sync(0xffffffffu, acc2, off);
            acc3 += __shfl_xor_sync(0xffffffffu, acc3, off);
        }
        if (lane == 0) {
            gates_s[warp * 4 + 0] = acc0;
            gates_s[warp * 4 + 1] = acc1;
            gates_s[warp * 4 + 2] = acc2;
            gates_s[warp * 4 + 3] = acc3;
        }
        __syncthreads();

        if (tid < 8) {
            float gi = fsigm(gates_s[tid]      + xgv0);
            float gf = fsigm(gates_s[8 + tid]  + xgv1);
            float gg = ftanh(gates_s[16 + tid] + xgv2);
            float go = fsigm(gates_s[24 + tid] + xgv3);
            c_state = gf * c_state + gi * gg;
            float hn = go * ftanh(c_state);
            __stcg(&g_h[t & 1][base + tid], hn);
        }
        __syncwarp();   // warp 0: h stores complete before flag release
        if (tid == 0) {
            unsigned nf = (unsigned)(t + 1);
            asm volatile("st.global.release.gpu.b32 [%0], %1;"
                         :: "l"(g_flag + blockIdx.x * FLAG_STRIDE), "r"(nf)
                         : "memory");
        }
        // No trailing barrier: independent-thread scheduling lets lanes 8-31
        // spin on next step's flags while lanes 0-7 publish; our own flag is
        // guaranteed to advance.
    }
}

// ---------------- kernel 3: attention head + outputs ---------------------
__global__ void __launch_bounds__(256) finalize_kernel(
    const float* __restrict__ attn_w,
    const float* __restrict__ attn_b,
    float* __restrict__ out)
{
    __shared__ float red[8];
    const int o   = blockIdx.x;      // 0..63
    const int tid = threadIdx.x;
    const float* h = g_h[1];         // h after t=1023 (1023&1 == 1)

    float s = 0.f;
    for (int k = tid; k < HID; k += 256)
        s = fmaf(h[k], attn_w[o * HID + k], s);
    #pragma unroll
    for (int off = 16; off; off >>= 1)
        s += __shfl_xor_sync(0xffffffffu, s, off);
    if ((tid & 31) == 0) red[tid >> 5] = s;
    __syncthreads();
    if (tid == 0) {
        float tot = 0.f;
        #pragma unroll
        for (int i = 0; i < 8; i++) tot += red[i];
        red[0] = 1.0f / (1.0f + expf(-(tot + attn_b[o])));  // precise exp here (cheap, off scan path)
    }
    __syncthreads();
    float a = red[0];
    for (int p = tid; p < 1024; p += 256)
        out[o * 1024 + p] = a;
    if (o == 0)
        for (int j = tid; j < HID; j += 256)
            out[65536 + j] = h[j];
}

// ---------------- launch -------------------------------------------------
extern "C" void kernel_launch(void* const* d_in, const int* in_sizes, int n_in,
                              void* d_out, int out_size)
{
    const int*   tok    = (const int*)  d_in[0];
    const float* emb    = (const float*)d_in[1];
    const float* w_ih   = (const float*)d_in[2];
    const float* w_hh   = (const float*)d_in[3];
    const float* b_ih   = (const float*)d_in[4];
    const float* b_hh   = (const float*)d_in[5];
    const float* attn_w = (const float*)d_in[6];
    const float* attn_b = (const float*)d_in[7];
    float* out = (float*)d_out;

    init_kernel<<<8, 256>>>();
    dim3 gg(GATES / 64, SEQ / 64);           // 32 x 16 blocks
    xgates_gemm<<<gg, 256>>>(tok, emb, w_ih, b_ih, b_hh);
    lstm_scan<<<G_CTAS, 256>>>(w_hh);
    finalize_kernel<<<64, 256>>>(attn_w, attn_b, out);
}

// round 4
// speedup vs baseline: 1.5270x; 1.5270x over previous
#include <cuda_runtime.h>

#define SEQ   1024
#define HID   512
#define GATES 2048
#define EMB   512
#define G_CTAS 64
#define UNITS_PER 8     // HID / G_CTAS
#define FLAG_STRIDE 32  // 128 B between flags -> distinct L2 lines
#define NREP 4          // h replicas to spread L2 line pressure

// ---------------- device scratch (static, no allocation) ----------------
__device__ float    g_xg[SEQ * GATES];          // 8 MB precomputed input gates
__device__ float    g_hrep[NREP][2][HID];       // replicated double-buffered h
__device__ unsigned g_flag[G_CTAS * FLAG_STRIDE];

__device__ __forceinline__ float fsigm(float x) {
    return 1.0f / (1.0f + __expf(-x));
}
__device__ __forceinline__ float ftanh(float x) {
    return 2.0f / (1.0f + __expf(-2.0f * x)) - 1.0f;
}

// ---------------- init: reset flags + zero h (runs every replay) ------
__global__ void init_kernel() {
    int t = blockIdx.x * blockDim.x + threadIdx.x;
    if (t < NREP * 2 * HID) ((float*)g_hrep)[t] = 0.0f;
    if (t < G_CTAS * FLAG_STRIDE) g_flag[t] = 0u;
}

// ---------------- kernel 1: x_gates = emb[tok] @ w_ih^T + (b_ih+b_hh) ---
__global__ void __launch_bounds__(256) xgates_gemm(
    const int*   __restrict__ tok,
    const float* __restrict__ emb,
    const float* __restrict__ w_ih,
    const float* __restrict__ b_ih,
    const float* __restrict__ b_hh)
{
    __shared__ float As[32][68];
    __shared__ float Bs[32][68];
    __shared__ int   stok[64];

    const int tid = threadIdx.x;
    const int bm = blockIdx.y * 64;
    const int bn = blockIdx.x * 64;

    if (tid < 64) stok[tid] = tok[bm + tid];
    __syncthreads();

    float acc[4][4];
    #pragma unroll
    for (int i = 0; i < 4; i++)
        #pragma unroll
        for (int j = 0; j < 4; j++) acc[i][j] = 0.0f;

    const int tr = tid >> 4;
    const int tc = tid & 15;

    for (int k0 = 0; k0 < EMB; k0 += 32) {
        #pragma unroll
        for (int i = 0; i < 2; i++) {
            int idx = tid + 256 * i;
            int row = idx & 63;
            int k4  = idx >> 6;
            float4 av = *reinterpret_cast<const float4*>(
                emb + (size_t)stok[row] * EMB + k0 + k4 * 4);
            As[k4*4+0][row] = av.x; As[k4*4+1][row] = av.y;
            As[k4*4+2][row] = av.z; As[k4*4+3][row] = av.w;
            float4 bv = *reinterpret_cast<const float4*>(
                w_ih + (size_t)(bn + row) * EMB + k0 + k4 * 4);
            Bs[k4*4+0][row] = bv.x; Bs[k4*4+1][row] = bv.y;
            Bs[k4*4+2][row] = bv.z; Bs[k4*4+3][row] = bv.w;
        }
        __syncthreads();

        #pragma unroll
        for (int kk = 0; kk < 32; kk++) {
            float4 a4 = *reinterpret_cast<const float4*>(&As[kk][tr * 4]);
            float4 b4 = *reinterpret_cast<const float4*>(&Bs[kk][tc * 4]);
            float a[4] = {a4.x, a4.y, a4.z, a4.w};
            float b[4] = {b4.x, b4.y, b4.z, b4.w};
            #pragma unroll
            for (int i = 0; i < 4; i++)
                #pragma unroll
                for (int j = 0; j < 4; j++)
                    acc[i][j] = fmaf(a[i], b[j], acc[i][j]);
        }
        __syncthreads();
    }

    const int gcol = bn + tc * 4;
    float4 bias;
    bias.x = b_ih[gcol + 0] + b_hh[gcol + 0];
    bias.y = b_ih[gcol + 1] + b_hh[gcol + 1];
    bias.z = b_ih[gcol + 2] + b_hh[gcol + 2];
    bias.w = b_ih[gcol + 3] + b_hh[gcol + 3];
    #pragma unroll
    for (int i = 0; i < 4; i++) {
        int trow = bm + tr * 4 + i;
        float4 v;
        v.x = acc[i][0] + bias.x;
        v.y = acc[i][1] + bias.y;
        v.z = acc[i][2] + bias.z;
        v.w = acc[i][3] + bias.w;
        *reinterpret_cast<float4*>(g_xg + (size_t)trow * GATES + gcol) = v;
    }
}

// ---------------- kernel 2: persistent LSTM scan -------------------------
// 64 CTAs x 256 threads, 8 hidden units per CTA (32 gate rows).
// KEY CHANGE vs prior rounds: h is staged GLOBAL->SMEM ONCE per CTA per step
// (128 threads, one float4 each), then all warps consume from smem. Previously
// all 8 warps redundantly re-read the 2 KB h vector from the same 16 L2 lines
// (1 MB/step on 16 lines -> per-slice LTS serialization ~2000 cyc/step).
// Producers also write h to NREP=4 replicas; CTA j reads replica j&3, spreading
// consumer reads across 4x more L2 lines.
// Weight/k layout: lane l owns k = l + 32*m (m=0..15) -> conflict-free LDS.
__global__ void __launch_bounds__(256, 1) lstm_scan(const float* __restrict__ w_hh)
{
    const int tid  = threadIdx.x;
    const int warp = tid >> 5;
    const int lane = tid & 31;
    const int base = blockIdx.x * UNITS_PER;
    const int rep  = blockIdx.x & (NREP - 1);

    // Preload weight slices into registers (stride-32 k layout).
    float w[4][16];
    #pragma unroll
    for (int q = 0; q < 4; q++) {
        int lr   = warp * 4 + q;                       // local row 0..31
        int grow = (lr >> 3) * HID + base + (lr & 7);  // gate*512 + base + unit
        const float* src = w_hh + (size_t)grow * HID + lane;
        #pragma unroll
        for (int m = 0; m < 16; m++) w[q][m] = src[32 * m];
    }

    __shared__ float sh_h[HID];
    __shared__ float gates_s[32];
    float c_state = 0.0f;

    for (int t = 0; t < SEQ; t++) {
        // xg loads are independent of the scan: issue before the poll.
        float xgv0 = 0.f, xgv1 = 0.f, xgv2 = 0.f, xgv3 = 0.f;
        if (tid < 8) {
            const float* xp = g_xg + (size_t)t * GATES + base + tid;
            xgv0 = __ldg(xp);
            xgv1 = __ldg(xp + 512);
            xgv2 = __ldg(xp + 1024);
            xgv3 = __ldg(xp + 1536);
        }

        // Wait for all producers to have published step t-1 (flag >= t).
        if (tid < G_CTAS) {
            const unsigned* fp = g_flag + tid * FLAG_STRIDE;
            unsigned v;
            do {
                asm volatile("ld.global.acquire.gpu.b32 %0, [%1];"
                             : "=r"(v) : "l"(fp) : "memory");
            } while (v < (unsigned)t);
        }
        __syncthreads();

        // Stage h_{t-1} (buf (t+1)&1) global -> smem, once per CTA.
        if (tid < 128) {
            const float4* hsrc =
                reinterpret_cast<const float4*>(g_hrep[rep][(t + 1) & 1]) + tid;
            float4 v = __ldcg(hsrc);
            *reinterpret_cast<float4*>(&sh_h[tid * 4]) = v;
        }
        __syncthreads();

        // Each lane's 16 k-values: k = lane + 32*m  (conflict-free LDS).
        float hv[16];
        #pragma unroll
        for (int m = 0; m < 16; m++) hv[m] = sh_h[lane + 32 * m];

        float acc0 = 0.f, acc1 = 0.f, acc2 = 0.f, acc3 = 0.f;
        #pragma unroll
        for (int m = 0; m < 16; m++) {
            float h = hv[m];
            acc0 = fmaf(w[0][m], h, acc0);
            acc1 = fmaf(w[1][m], h, acc1);
            acc2 = fmaf(w[2][m], h, acc2);
            acc3 = fmaf(w[3][m], h, acc3);
        }
        #pragma unroll
        for (int off = 16; off; off >>= 1) {
            acc0 += __shfl_xor_sync(0xffffffffu, acc0, off);
            acc1 += __shfl_xor_sync(0xffffffffu, acc1, off);
            acc2 += __shfl_xor_sync(0xffffffffu, acc2, off);
            acc3 += __shfl_xor_sync(0xffffffffu, acc3, off);
        }
        if (lane == 0) {
            gates_s[warp * 4 + 0] = acc0;
            gates_s[warp * 4 + 1] = acc1;
            gates_s[warp * 4 + 2] = acc2;
            gates_s[warp * 4 + 3] = acc3;
        }
        __syncthreads();

        if (tid < 8) {
            float gi = fsigm(gates_s[tid]      + xgv0);
            float gf = fsigm(gates_s[8 + tid]  + xgv1);
            float gg = ftanh(gates_s[16 + tid] + xgv2);
            float go = fsigm(gates_s[24 + tid] + xgv3);
            c_state = gf * c_state + gi * gg;
            float hn = go * ftanh(c_state);
            #pragma unroll
            for (int r = 0; r < NREP; r++)
                __stcg(&g_hrep[r][t & 1][base + tid], hn);
        }
        __syncwarp();   // producers (warp 0) done before flag release
        if (tid == 0) {
            unsigned nf = (unsigned)(t + 1);
            asm volatile("st.global.release.gpu.b32 [%0], %1;"
                         :: "l"(g_flag + blockIdx.x * FLAG_STRIDE), "r"(nf)
                         : "memory");
        }
        // No trailing CTA barrier needed: next-step __syncthreads (after poll)
        // re-converges; own flag is guaranteed to advance.
        __syncthreads();
    }
}

// ---------------- kernel 3: attention head + outputs ---------------------
__global__ void __launch_bounds__(256) finalize_kernel(
    const float* __restrict__ attn_w,
    const float* __restrict__ attn_b,
    float* __restrict__ out)
{
    __shared__ float red[8];
    const int o   = blockIdx.x;      // 0..63
    const int tid = threadIdx.x;
    const float* h = g_hrep[0][1];   // h after t=1023 (1023&1 == 1)

    float s = 0.f;
    for (int k = tid; k < HID; k += 256)
        s = fmaf(h[k], attn_w[o * HID + k], s);
    #pragma unroll
    for (int off = 16; off; off >>= 1)
        s += __shfl_xor_sync(0xffffffffu, s, off);
    if ((tid & 31) == 0) red[tid >> 5] = s;
    __syncthreads();
    if (tid == 0) {
        float tot = 0.f;
        #pragma unroll
        for (int i = 0; i < 8; i++) tot += red[i];
        red[0] = 1.0f / (1.0f + expf(-(tot + attn_b[o])));
    }
    __syncthreads();
    float a = red[0];
    for (int p = tid; p < 1024; p += 256)
        out[o * 1024 + p] = a;
    if (o == 0)
        for (int j = tid; j < HID; j += 256)
            out[65536 + j] = h[j];
}

// ---------------- launch -------------------------------------------------
extern "C" void kernel_launch(void* const* d_in, const int* in_sizes, int n_in,
                              void* d_out, int out_size)
{
    const int*   tok    = (const int*)  d_in[0];
    const float* emb    = (const float*)d_in[1];
    const float* w_ih   = (const float*)d_in[2];
    const float* w_hh   = (const float*)d_in[3];
    const float* b_ih   = (const float*)d_in[4];
    const float* b_hh   = (const float*)d_in[5];
    const float* attn_w = (const float*)d_in[6];
    const float* attn_b = (const float*)d_in[7];
    float* out = (float*)d_out;

    init_kernel<<<18, 256>>>();
    dim3 gg(GATES / 64, SEQ / 64);           // 32 x 16 blocks
    xgates_gemm<<<gg, 256>>>(tok, emb, w_ih, b_ih, b_hh);
    lstm_scan<<<G_CTAS, 256>>>(w_hh);
    finalize_kernel<<<64, 256>>>(attn_w, attn_b, out);
}

// round 7
// speedup vs baseline: 1.7293x; 1.1325x over previous
#include <cuda_runtime.h>

#define SEQ   1024
#define HID   512
#define GATES 2048
#define EMB   512
#define G_CTAS 64
#define UNITS_PER 8     // HID / G_CTAS
#define FLAG_STRIDE 32  // 128 B between flags -> distinct L2 lines
#define NREP 8          // replicas of the tagged h stream
#define NBUF 8          // tagged ring depth (power of 2)

// ---------------- device scratch (static, no allocation) ----------------
__device__ float g_xg[SEQ * GATES];                 // 8 MB precomputed input gates
// Tagged h stream: each 64-bit word = {tag:32 | value:32}. Word for unit u of
// h_t lives at slot t&(NBUF-1), tag = t+1 (init zeros = h_{-1} with tag 0).
__device__ unsigned long long g_hp[NBUF][NREP][HID];
__device__ unsigned g_flag[G_CTAS * FLAG_STRIDE];   // backward-edge step counters

__device__ __forceinline__ float fsigm(float x) {
    return 1.0f / (1.0f + __expf(-x));
}
__device__ __forceinline__ float ftanh(float x) {
    return 2.0f / (1.0f + __expf(-2.0f * x)) - 1.0f;
}

// ---------------- init: zero tagged ring + flags (runs every replay) ----
__global__ void init_kernel() {
    int t = blockIdx.x * blockDim.x + threadIdx.x;
    int nwords = NBUF * NREP * HID;                 // 32768 u64
    if (t < nwords) ((unsigned long long*)g_hp)[t] = 0ull;
    if (t < G_CTAS * FLAG_STRIDE) g_flag[t] = 0u;
}

// ---------------- kernel 1: x_gates = emb[tok] @ w_ih^T + (b_ih+b_hh) ---
__global__ void __launch_bounds__(256) xgates_gemm(
    const int*   __restrict__ tok,
    const float* __restrict__ emb,
    const float* __restrict__ w_ih,
    const float* __restrict__ b_ih,
    const float* __restrict__ b_hh)
{
    __shared__ float As[32][68];
    __shared__ float Bs[32][68];
    __shared__ int   stok[64];

    const int tid = threadIdx.x;
    const int bm = blockIdx.y * 64;
    const int bn = blockIdx.x * 64;

    if (tid < 64) stok[tid] = tok[bm + tid];
    __syncthreads();

    float acc[4][4];
    #pragma unroll
    for (int i = 0; i < 4; i++)
        #pragma unroll
        for (int j = 0; j < 4; j++) acc[i][j] = 0.0f;

    const int tr = tid >> 4;
    const int tc = tid & 15;

    for (int k0 = 0; k0 < EMB; k0 += 32) {
        #pragma unroll
        for (int i = 0; i < 2; i++) {
            int idx = tid + 256 * i;
            int row = idx & 63;
            int k4  = idx >> 6;
            float4 av = *reinterpret_cast<const float4*>(
                emb + (size_t)stok[row] * EMB + k0 + k4 * 4);
            As[k4*4+0][row] = av.x; As[k4*4+1][row] = av.y;
            As[k4*4+2][row] = av.z; As[k4*4+3][row] = av.w;
            float4 bv = *reinterpret_cast<const float4*>(
                w_ih + (size_t)(bn + row) * EMB + k0 + k4 * 4);
            Bs[k4*4+0][row] = bv.x; Bs[k4*4+1][row] = bv.y;
            Bs[k4*4+2][row] = bv.z; Bs[k4*4+3][row] = bv.w;
        }
        __syncthreads();

        #pragma unroll
        for (int kk = 0; kk < 32; kk++) {
            float4 a4 = *reinterpret_cast<const float4*>(&As[kk][tr * 4]);
            float4 b4 = *reinterpret_cast<const float4*>(&Bs[kk][tc * 4]);
            float a[4] = {a4.x, a4.y, a4.z, a4.w};
            float b[4] = {b4.x, b4.y, b4.z, b4.w};
            #pragma unroll
            for (int i = 0; i < 4; i++)
                #pragma unroll
                for (int j = 0; j < 4; j++)
                    acc[i][j] = fmaf(a[i], b[j], acc[i][j]);
        }
        __syncthreads();
    }

    const int gcol = bn + tc * 4;
    float4 bias;
    bias.x = b_ih[gcol + 0] + b_hh[gcol + 0];
    bias.y = b_ih[gcol + 1] + b_hh[gcol + 1];
    bias.z = b_ih[gcol + 2] + b_hh[gcol + 2];
    bias.w = b_ih[gcol + 3] + b_hh[gcol + 3];
    #pragma unroll
    for (int i = 0; i < 4; i++) {
        int trow = bm + tr * 4 + i;
        float4 v;
        v.x = acc[i][0] + bias.x;
        v.y = acc[i][1] + bias.y;
        v.z = acc[i][2] + bias.z;
        v.w = acc[i][3] + bias.w;
        *reinterpret_cast<float4*>(g_xg + (size_t)trow * GATES + gcol) = v;
    }
}

// ---------------- kernel 2: persistent LSTM scan (tagged dataflow) -------
// 64 CTAs x 256 threads, 8 hidden units per CTA (32 gate rows).
// Sync fused into data: producers publish (tag<<32 | h_bits) with a single
// MORALLY-STRONG st.global.relaxed.gpu.b64; consumers spin with matching
// ld.global.relaxed.gpu.b64. Per the PTX memory model, single-copy atomicity
// holds only between morally strong ops of equal size — R5 (weak v4.u32) and
// R6 (weak .cg u64) were both permitted to observe torn (new-tag, old-value)
// mixes; relaxed.gpu ops of 8 bytes cannot tear. Relaxed ordering suffices:
// the protected datum is the loaded word itself. Ring depth NBUF=8 prevents
// overwrite races via an off-critical-path backward edge: before writing
// slot t, all per-CTA flags must be >= t-6 (6 steps stale -> first poll
// passes in steady state). Deadlock-free: the slowest CTA's dependencies are
// strictly older than itself.
__global__ void __launch_bounds__(256, 1) lstm_scan(const float* __restrict__ w_hh)
{
    const int tid  = threadIdx.x;
    const int warp = tid >> 5;
    const int lane = tid & 31;
    const int base = blockIdx.x * UNITS_PER;
    const int rep  = blockIdx.x & (NREP - 1);

    // Preload weight slices into registers (stride-32 k layout:
    // lane l owns k = l + 32*m -> conflict-free LDS of staged h).
    float w[4][16];
    #pragma unroll
    for (int q = 0; q < 4; q++) {
        int lr   = warp * 4 + q;                       // local row 0..31
        int grow = (lr >> 3) * HID + base + (lr & 7);  // gate*512 + base + unit
        const float* src = w_hh + (size_t)grow * HID + lane;
        #pragma unroll
        for (int m = 0; m < 16; m++) w[q][m] = src[32 * m];
    }

    __shared__ float sh_h[HID];
    __shared__ float gates_s[32];
    float c_state = 0.0f;

    for (int t = 0; t < SEQ; t++) {
        // xg loads: independent of the scan, issue first (L2-resident).
        float xgv0 = 0.f, xgv1 = 0.f, xgv2 = 0.f, xgv3 = 0.f;
        if (tid < 8) {
            const float* xp = g_xg + (size_t)t * GATES + base + tid;
            xgv0 = __ldg(xp);
            xgv1 = __ldg(xp + 512);
            xgv2 = __ldg(xp + 1024);
            xgv3 = __ldg(xp + 1536);
        }

        // Backward edge (write-safety for slot t): all flags >= t-6.
        if (t >= 7 && tid < G_CTAS) {
            const unsigned* fp = g_flag + tid * FLAG_STRIDE;
            unsigned tgt = (unsigned)(t - 6);
            unsigned v;
            do {
                asm volatile("ld.global.acquire.gpu.b32 %0, [%1];"
                             : "=r"(v) : "l"(fp) : "memory");
            } while (v < tgt);
        }

        // Data poll: h_{t-1} words carry tag == t. Each thread owns 2 units;
        // morally-strong relaxed 8-byte loads -> (value,tag) cannot tear.
        {
            const unsigned long long* p =
                &g_hp[(t + NBUF - 1) & (NBUF - 1)][rep][tid * 2];
            unsigned long long p0, p1;
            unsigned tg = (unsigned)t;
            do {
                asm volatile("ld.global.relaxed.gpu.b64 %0, [%1];"
                             : "=l"(p0) : "l"(p) : "memory");
            } while ((unsigned)(p0 >> 32) != tg);
            do {
                asm volatile("ld.global.relaxed.gpu.b64 %0, [%1];"
                             : "=l"(p1) : "l"(p + 1) : "memory");
            } while ((unsigned)(p1 >> 32) != tg);
            sh_h[tid * 2 + 0] = __uint_as_float((unsigned)p0);
            sh_h[tid * 2 + 1] = __uint_as_float((unsigned)p1);
        }
        __syncthreads();

        // Each lane's 16 k-values: k = lane + 32*m (conflict-free LDS).
        float acc0 = 0.f, acc1 = 0.f, acc2 = 0.f, acc3 = 0.f;
        #pragma unroll
        for (int m = 0; m < 16; m++) {
            float h = sh_h[lane + 32 * m];
            acc0 = fmaf(w[0][m], h, acc0);
            acc1 = fmaf(w[1][m], h, acc1);
            acc2 = fmaf(w[2][m], h, acc2);
            acc3 = fmaf(w[3][m], h, acc3);
        }
        #pragma unroll
        for (int off = 16; off; off >>= 1) {
            acc0 += __shfl_xor_sync(0xffffffffu, acc0, off);
            acc1 += __shfl_xor_sync(0xffffffffu, acc1, off);
            acc2 += __shfl_xor_sync(0xffffffffu, acc2, off);
            acc3 += __shfl_xor_sync(0xffffffffu, acc3, off);
        }
        if (lane == 0) {
            gates_s[warp * 4 + 0] = acc0;
            gates_s[warp * 4 + 1] = acc1;
            gates_s[warp * 4 + 2] = acc2;
            gates_s[warp * 4 + 3] = acc3;
        }
        __syncthreads();

        if (tid < 8) {
            float gi = fsigm(gates_s[tid]      + xgv0);
            float gf = fsigm(gates_s[8 + tid]  + xgv1);
            float gg = ftanh(gates_s[16 + tid] + xgv2);
            float go = fsigm(gates_s[24 + tid] + xgv3);
            c_state = gf * c_state + gi * gg;
            float hn = go * ftanh(c_state);

            // Publish (tag=t+1, value): one morally-strong u64 per replica.
            unsigned long long pk =
                ((unsigned long long)(unsigned)(t + 1) << 32) |
                (unsigned long long)__float_as_uint(hn);
            int slot = t & (NBUF - 1);
            int unit = base + tid;
            #pragma unroll
            for (int r = 0; r < NREP; r++) {
                unsigned long long* dst = &g_hp[slot][r][unit];
                asm volatile("st.global.relaxed.gpu.b64 [%0], %1;"
                             :: "l"(dst), "l"(pk) : "memory");
            }
        }
        __syncwarp();
        if (tid == 0) {
            unsigned nf = (unsigned)(t + 1);
            asm volatile("st.global.release.gpu.b32 [%0], %1;"
                         :: "l"(g_flag + blockIdx.x * FLAG_STRIDE), "r"(nf)
                         : "memory");
        }
        __syncthreads();
    }
}

// ---------------- kernel 3: attention head + outputs ---------------------
__global__ void __launch_bounds__(256) finalize_kernel(
    const float* __restrict__ attn_w,
    const float* __restrict__ attn_b,
    float* __restrict__ out)
{
    __shared__ float red[8];
    const int o   = blockIdx.x;      // 0..63
    const int tid = threadIdx.x;
    // h_1023 lives in slot 1023&7 == 7, replica 0, tagged words.
    const unsigned long long* hp = &g_hp[7][0][0];

    float s = 0.f;
    for (int k = tid; k < HID; k += 256)
        s = fmaf(__uint_as_float((unsigned)hp[k]), attn_w[o * HID + k], s);
    #pragma unroll
    for (int off = 16; off; off >>= 1)
        s += __shfl_xor_sync(0xffffffffu, s, off);
    if ((tid & 31) == 0) red[tid >> 5] = s;
    __syncthreads();
    if (tid == 0) {
        float tot = 0.f;
        #pragma unroll
        for (int i = 0; i < 8; i++) tot += red[i];
        red[0] = 1.0f / (1.0f + expf(-(tot + attn_b[o])));
    }
    __syncthreads();
    float a = red[0];
    for (int p = tid; p < 1024; p += 256)
        out[o * 1024 + p] = a;
    if (o == 0)
        for (int j = tid; j < HID; j += 256)
            out[65536 + j] = __uint_as_float((unsigned)hp[j]);
}

// ---------------- launch -------------------------------------------------
extern "C" void kernel_launch(void* const* d_in, const int* in_sizes, int n_in,
                              void* d_out, int out_size)
{
    const int*   tok    = (const int*)  d_in[0];
    const float* emb    = (const float*)d_in[1];
    const float* w_ih   = (const float*)d_in[2];
    const float* w_hh   = (const float*)d_in[3];
    const float* b_ih   = (const float*)d_in[4];
    const float* b_hh   = (const float*)d_in[5];
    const float* attn_w = (const float*)d_in[6];
    const float* attn_b = (const float*)d_in[7];
    float* out = (float*)d_out;

    init_kernel<<<128, 256>>>();
    dim3 gg(GATES / 64, SEQ / 64);           // 32 x 16 blocks
    xgates_gemm<<<gg, 256>>>(tok, emb, w_ih, b_ih, b_hh);
    lstm_scan<<<G_CTAS, 256>>>(w_hh);
    finalize_kernel<<<64, 256>>>(attn_w, attn_b, out);
}

// round 9
// speedup vs baseline: 2.0411x; 1.1803x over previous
#include <cuda_runtime.h>

#define SEQ   1024
#define HID   512
#define GATES 2048
#define EMB   512
#define G_CTAS 64
#define UNITS_PER 8     // HID / G_CTAS == warps per CTA
#define NREP 8          // replicas of the tagged h stream
#define NBUF 8          // tagged ring depth (power of 2)

// ---------------- device scratch (static, no allocation) ----------------
__device__ float g_xg[SEQ * GATES];              // 8 MB precomputed input gates
// Tagged h stream: 64-bit word = {tag:32 | value:32}. Word for unit u of h_t
// lives at slot t&(NBUF-1), tag = t+1. Init zeros = h_{-1} with tag 0.
__device__ unsigned long long g_hp[NBUF][NREP][HID];

__device__ __forceinline__ float fsigm(float x) {
    return 1.0f / (1.0f + __expf(-x));
}
__device__ __forceinline__ float ftanh(float x) {
    return 2.0f / (1.0f + __expf(-2.0f * x)) - 1.0f;
}

__device__ __forceinline__ unsigned long long ldg_strong(
    const unsigned long long* p) {
    unsigned long long v;
    asm volatile("ld.global.relaxed.gpu.b64 %0, [%1];"
                 : "=l"(v) : "l"(p) : "memory");
    return v;
}
__device__ __forceinline__ void stg_strong(unsigned long long* p,
                                           unsigned long long v) {
    asm volatile("st.global.relaxed.gpu.b64 [%0], %1;"
                 :: "l"(p), "l"(v) : "memory");
}

// ---------------- init: zero tagged ring (runs every replay) ------------
__global__ void init_kernel() {
    int t = blockIdx.x * blockDim.x + threadIdx.x;
    int nwords = NBUF * NREP * HID;              // 32768 u64
    if (t < nwords) ((unsigned long long*)g_hp)[t] = 0ull;
}

// ---------------- kernel 1: x_gates = emb[tok] @ w_ih^T + (b_ih+b_hh) ---
__global__ void __launch_bounds__(256) xgates_gemm(
    const int*   __restrict__ tok,
    const float* __restrict__ emb,
    const float* __restrict__ w_ih,
    const float* __restrict__ b_ih,
    const float* __restrict__ b_hh)
{
    __shared__ float As[32][68];
    __shared__ float Bs[32][68];
    __shared__ int   stok[64];

    const int tid = threadIdx.x;
    const int bm = blockIdx.y * 64;
    const int bn = blockIdx.x * 64;

    if (tid < 64) stok[tid] = tok[bm + tid];
    __syncthreads();

    float acc[4][4];
    #pragma unroll
    for (int i = 0; i < 4; i++)
        #pragma unroll
        for (int j = 0; j < 4; j++) acc[i][j] = 0.0f;

    const int tr = tid >> 4;
    const int tc = tid & 15;

    for (int k0 = 0; k0 < EMB; k0 += 32) {
        #pragma unroll
        for (int i = 0; i < 2; i++) {
            int idx = tid + 256 * i;
            int row = idx & 63;
            int k4  = idx >> 6;
            float4 av = *reinterpret_cast<const float4*>(
                emb + (size_t)stok[row] * EMB + k0 + k4 * 4);
            As[k4*4+0][row] = av.x; As[k4*4+1][row] = av.y;
            As[k4*4+2][row] = av.z; As[k4*4+3][row] = av.w;
            float4 bv = *reinterpret_cast<const float4*>(
                w_ih + (size_t)(bn + row) * EMB + k0 + k4 * 4);
            Bs[k4*4+0][row] = bv.x; Bs[k4*4+1][row] = bv.y;
            Bs[k4*4+2][row] = bv.z; Bs[k4*4+3][row] = bv.w;
        }
        __syncthreads();

        #pragma unroll
        for (int kk = 0; kk < 32; kk++) {
            float4 a4 = *reinterpret_cast<const float4*>(&As[kk][tr * 4]);
            float4 b4 = *reinterpret_cast<const float4*>(&Bs[kk][tc * 4]);
            float a[4] = {a4.x, a4.y, a4.z, a4.w};
            float b[4] = {b4.x, b4.y, b4.z, b4.w};
            #pragma unroll
            for (int i = 0; i < 4; i++)
                #pragma unroll
                for (int j = 0; j < 4; j++)
                    acc[i][j] = fmaf(a[i], b[j], acc[i][j]);
        }
        __syncthreads();
    }

    const int gcol = bn + tc * 4;
    float4 bias;
    bias.x = b_ih[gcol + 0] + b_hh[gcol + 0];
    bias.y = b_ih[gcol + 1] + b_hh[gcol + 1];
    bias.z = b_ih[gcol + 2] + b_hh[gcol + 2];
    bias.w = b_ih[gcol + 3] + b_hh[gcol + 3];
    #pragma unroll
    for (int i = 0; i < 4; i++) {
        int trow = bm + tr * 4 + i;
        float4 v;
        v.x = acc[i][0] + bias.x;
        v.y = acc[i][1] + bias.y;
        v.z = acc[i][2] + bias.z;
        v.w = acc[i][3] + bias.w;
        *reinterpret_cast<float4*>(g_xg + (size_t)trow * GATES + gcol) = v;
    }
}

// ---------------- kernel 2: persistent LSTM scan ------------------------
// 64 CTAs x 256 threads; warp w owns unit u = base + w. ONE __syncthreads
// per step:
//   Phase A (stage): each thread polls its 2 assigned tagged global words
//     (morally-strong relaxed u64 -> no tearing); on tag==t stores the f32
//     VALUE into double-buffered sh_h[t&1]. The only spin is on GLOBAL
//     words written by last iteration's publishers (proven pattern, R7).
//   __syncthreads -> all 512 smem h values verified; no smem spins ever.
//   Phase B (compute): warp w does 64 FMAs against register weights,
//     full-butterfly reduce (all lanes get all 4 sums), every lane
//     redundantly computes gates/c/h, lanes 0..7 publish the 8 replicas in
//     parallel. No gates smem, no serial tail, no trailing barrier.
// Safety: stagers write smem only after tag-match; staging sh[t&1] at
// iteration t+2 requires chip-wide tags t+2, which requires this CTA's own
// warps to have published t+1, hence finished reading sh[t&1]. Every wait
// depends only on strictly-earlier iterations -> deadlock-free; base case
// is the zeroed ring (tag 0 = h_{-1}).
__global__ void __launch_bounds__(256, 1) lstm_scan(const float* __restrict__ w_hh)
{
    const int tid  = threadIdx.x;
    const int warp = tid >> 5;
    const int lane = tid & 31;
    const int base = blockIdx.x * UNITS_PER;
    const int unit = base + warp;
    const int rep  = blockIdx.x & (NREP - 1);

    // Weight rows for this warp's unit: gate q row = q*512 + unit.
    // Lane l holds k = l + 32m (conflict-free LDS of staged h).
    float w[4][16];
    #pragma unroll
    for (int q = 0; q < 4; q++) {
        const float* src = w_hh + (size_t)(q * HID + unit) * HID + lane;
        #pragma unroll
        for (int m = 0; m < 16; m++) w[q][m] = src[32 * m];
    }

    __shared__ float sh_h[2][HID];
    float c_state = 0.0f;

    for (int t = 0; t < SEQ; t++) {
        const unsigned tg = (unsigned)t;
        float* shb = sh_h[t & 1];

        // xg prefetch: all 32 lanes load the same 4 addresses (broadcast).
        const float* xp = g_xg + (size_t)t * GATES + unit;
        float xg0 = __ldg(xp);
        float xg1 = __ldg(xp + 512);
        float xg2 = __ldg(xp + 1024);
        float xg3 = __ldg(xp + 1536);

        // Phase A: poll 2 tagged words, stage values to smem on match.
        {
            const unsigned long long* gp =
                &g_hp[(t + NBUF - 1) & (NBUF - 1)][rep][tid * 2];
            unsigned long long p0 = ldg_strong(gp);
            unsigned long long p1 = ldg_strong(gp + 1);
            while ((unsigned)(p0 >> 32) != tg) p0 = ldg_strong(gp);
            shb[tid * 2] = __uint_as_float((unsigned)p0);
            while ((unsigned)(p1 >> 32) != tg) p1 = ldg_strong(gp + 1);
            shb[tid * 2 + 1] = __uint_as_float((unsigned)p1);
        }
        __syncthreads();

        // Phase B: 4 gate dots + full-butterfly reduce.
        float a0 = 0.f, a1 = 0.f, a2 = 0.f, a3 = 0.f;
        #pragma unroll
        for (int m = 0; m < 16; m++) {
            float h = shb[lane + 32 * m];
            a0 = fmaf(w[0][m], h, a0);
            a1 = fmaf(w[1][m], h, a1);
            a2 = fmaf(w[2][m], h, a2);
            a3 = fmaf(w[3][m], h, a3);
        }
        #pragma unroll
        for (int off = 16; off; off >>= 1) {
            a0 += __shfl_xor_sync(0xffffffffu, a0, off);
            a1 += __shfl_xor_sync(0xffffffffu, a1, off);
            a2 += __shfl_xor_sync(0xffffffffu, a2, off);
            a3 += __shfl_xor_sync(0xffffffffu, a3, off);
        }

        // All lanes redundantly compute gates (same inputs, deterministic).
        float gi = fsigm(a0 + xg0);
        float gf = fsigm(a1 + xg1);
        float gg = ftanh(a2 + xg2);
        float go = fsigm(a3 + xg3);
        c_state = gf * c_state + gi * gg;
        float hn = go * ftanh(c_state);

        // Publish: lanes 0..NREP-1 store the replicas in parallel.
        unsigned long long pk =
            ((unsigned long long)(tg + 1u) << 32) |
            (unsigned long long)__float_as_uint(hn);
        if (lane < NREP)
            stg_strong(&g_hp[t & (NBUF - 1)][lane][unit], pk);
    }
}

// ---------------- kernel 3: attention head + outputs ---------------------
__global__ void __launch_bounds__(256) finalize_kernel(
    const float* __restrict__ attn_w,
    const float* __restrict__ attn_b,
    float* __restrict__ out)
{
    __shared__ float red[8];
    const int o   = blockIdx.x;      // 0..63
    const int tid = threadIdx.x;
    // h_1023 lives in slot 1023&7 == 7, replica 0, tagged words.
    const unsigned long long* hp = &g_hp[7][0][0];

    float s = 0.f;
    for (int k = tid; k < HID; k += 256)
        s = fmaf(__uint_as_float((unsigned)hp[k]), attn_w[o * HID + k], s);
    #pragma unroll
    for (int off = 16; off; off >>= 1)
        s += __shfl_xor_sync(0xffffffffu, s, off);
    if ((tid & 31) == 0) red[tid >> 5] = s;
    __syncthreads();
    if (tid == 0) {
        float tot = 0.f;
        #pragma unroll
        for (int i = 0; i < 8; i++) tot += red[i];
        red[0] = 1.0f / (1.0f + expf(-(tot + attn_b[o])));
    }
    __syncthreads();
    float a = red[0];
    for (int p = tid; p < 1024; p += 256)
        out[o * 1024 + p] = a;
    if (o == 0)
        for (int j = tid; j < HID; j += 256)
            out[65536 + j] = __uint_as_float((unsigned)hp[j]);
}

// ---------------- launch -------------------------------------------------
extern "C" void kernel_launch(void* const* d_in, const int* in_sizes, int n_in,
                              void* d_out, int out_size)
{
    const int*   tok    = (const int*)  d_in[0];
    const float* emb    = (const float*)d_in[1];
    const float* w_ih   = (const float*)d_in[2];
    const float* w_hh   = (const float*)d_in[3];
    const float* b_ih   = (const float*)d_in[4];
    const float* b_hh   = (const float*)d_in[5];
    const float* attn_w = (const float*)d_in[6];
    const float* attn_b = (const float*)d_in[7];
    float* out = (float*)d_out;

    init_kernel<<<128, 256>>>();
    dim3 gg(GATES / 64, SEQ / 64);           // 32 x 16 blocks
    xgates_gemm<<<gg, 256>>>(tok, emb, w_ih, b_ih, b_hh);
    lstm_scan<<<G_CTAS, 256>>>(w_hh);
    finalize_kernel<<<64, 256>>>(attn_w, attn_b, out);
}

// round 10
// speedup vs baseline: 2.4300x; 1.1905x over previous
#include <cuda_runtime.h>

#define SEQ   1024
#define HID   512
#define GATES 2048
#define EMB   512
#define G_CTAS 64
#define UNITS_PER 8     // HID / G_CTAS == warps per CTA
#define NREP 8          // replicas of the tagged h stream
#define NBUF 8          // tagged ring depth (power of 2)

// ---------------- device scratch (static, no allocation) ----------------
__device__ float g_xg[SEQ * GATES];              // 8 MB precomputed input gates
// Tagged h stream: 64-bit word = {tag:32 | value:32}. Word for unit u of h_t
// lives at slot t&(NBUF-1), tag = t+1. Zeroed state = h_{-1} with tag 0.
// Zero-init at module load; re-zeroed by xgates_gemm every call.
__device__ unsigned long long g_hp[NBUF][NREP][HID];

__device__ __forceinline__ float fsigm(float x) {
    return 1.0f / (1.0f + __expf(-x));
}
__device__ __forceinline__ float ftanh(float x) {
    return 2.0f / (1.0f + __expf(-2.0f * x)) - 1.0f;
}

__device__ __forceinline__ unsigned long long ldg_strong(
    const unsigned long long* p) {
    unsigned long long v;
    asm volatile("ld.global.relaxed.gpu.b64 %0, [%1];"
                 : "=l"(v) : "l"(p) : "memory");
    return v;
}
__device__ __forceinline__ void stg_strong(unsigned long long* p,
                                           unsigned long long v) {
    asm volatile("st.global.relaxed.gpu.b64 [%0], %1;"
                 :: "l"(p), "l"(v) : "memory");
}

// ---------------- kernel 1: x_gates GEMM + ring re-init ------------------
// Also re-zeroes the tagged ring for the NEXT scan launch (first 128 blocks,
// one u64 per thread: 128*256 = 32768 = NBUF*NREP*HID words).
__global__ void __launch_bounds__(256) xgates_gemm(
    const int*   __restrict__ tok,
    const float* __restrict__ emb,
    const float* __restrict__ w_ih,
    const float* __restrict__ b_ih,
    const float* __restrict__ b_hh)
{
    __shared__ float As[32][68];
    __shared__ float Bs[32][68];
    __shared__ int   stok[64];

    const int tid = threadIdx.x;
    const int bm = blockIdx.y * 64;
    const int bn = blockIdx.x * 64;

    {   // ring re-init (module-load zeroing covers the very first call)
        int bid = blockIdx.y * gridDim.x + blockIdx.x;
        if (bid < 128)
            ((unsigned long long*)g_hp)[bid * 256 + tid] = 0ull;
    }

    if (tid < 64) stok[tid] = tok[bm + tid];
    __syncthreads();

    float acc[4][4];
    #pragma unroll
    for (int i = 0; i < 4; i++)
        #pragma unroll
        for (int j = 0; j < 4; j++) acc[i][j] = 0.0f;

    const int tr = tid >> 4;
    const int tc = tid & 15;

    for (int k0 = 0; k0 < EMB; k0 += 32) {
        #pragma unroll
        for (int i = 0; i < 2; i++) {
            int idx = tid + 256 * i;
            int row = idx & 63;
            int k4  = idx >> 6;
            float4 av = *reinterpret_cast<const float4*>(
                emb + (size_t)stok[row] * EMB + k0 + k4 * 4);
            As[k4*4+0][row] = av.x; As[k4*4+1][row] = av.y;
            As[k4*4+2][row] = av.z; As[k4*4+3][row] = av.w;
            float4 bv = *reinterpret_cast<const float4*>(
                w_ih + (size_t)(bn + row) * EMB + k0 + k4 * 4);
            Bs[k4*4+0][row] = bv.x; Bs[k4*4+1][row] = bv.y;
            Bs[k4*4+2][row] = bv.z; Bs[k4*4+3][row] = bv.w;
        }
        __syncthreads();

        #pragma unroll
        for (int kk = 0; kk < 32; kk++) {
            float4 a4 = *reinterpret_cast<const float4*>(&As[kk][tr * 4]);
            float4 b4 = *reinterpret_cast<const float4*>(&Bs[kk][tc * 4]);
            float a[4] = {a4.x, a4.y, a4.z, a4.w};
            float b[4] = {b4.x, b4.y, b4.z, b4.w};
            #pragma unroll
            for (int i = 0; i < 4; i++)
                #pragma unroll
                for (int j = 0; j < 4; j++)
                    acc[i][j] = fmaf(a[i], b[j], acc[i][j]);
        }
        __syncthreads();
    }

    const int gcol = bn + tc * 4;
    float4 bias;
    bias.x = b_ih[gcol + 0] + b_hh[gcol + 0];
    bias.y = b_ih[gcol + 1] + b_hh[gcol + 1];
    bias.z = b_ih[gcol + 2] + b_hh[gcol + 2];
    bias.w = b_ih[gcol + 3] + b_hh[gcol + 3];
    #pragma unroll
    for (int i = 0; i < 4; i++) {
        int trow = bm + tr * 4 + i;
        float4 v;
        v.x = acc[i][0] + bias.x;
        v.y = acc[i][1] + bias.y;
        v.z = acc[i][2] + bias.z;
        v.w = acc[i][3] + bias.w;
        *reinterpret_cast<float4*>(g_xg + (size_t)trow * GATES + gcol) = v;
    }
}

// ---------------- kernel 2: persistent LSTM scan + fused attention head --
// 64 CTAs x 256 threads; warp w owns unit u = base + w. ONE __syncthreads
// per step. Phase A uses PIPELINED POLLING: each spin iteration issues a
// batch of 4 independent relaxed u64 loads per word (LDG issue floor 4 cyc),
// cutting the flag-sampling granularity from one L2 round trip (~300 cyc)
// to ~60 cyc. Tags are monotonic and each matched sample carries the unique
// value for that tag, so accepting any matching sample is safe.
// After the loop: stage h_1023 (tag 1024, slot 7), then CTA j computes
// attention output unit j from smem and CTA 0 emits the h copy — finalize
// kernel eliminated.
__global__ void __launch_bounds__(256, 1) lstm_scan(
    const float* __restrict__ w_hh,
    const float* __restrict__ attn_w,
    const float* __restrict__ attn_b,
    float*       __restrict__ out)
{
    const int tid  = threadIdx.x;
    const int warp = tid >> 5;
    const int lane = tid & 31;
    const int base = blockIdx.x * UNITS_PER;
    const int unit = base + warp;
    const int rep  = blockIdx.x & (NREP - 1);

    // Weight rows for this warp's unit: gate q row = q*512 + unit.
    // Lane l holds k = l + 32m (conflict-free LDS of staged h).
    float w[4][16];
    #pragma unroll
    for (int q = 0; q < 4; q++) {
        const float* src = w_hh + (size_t)(q * HID + unit) * HID + lane;
        #pragma unroll
        for (int m = 0; m < 16; m++) w[q][m] = src[32 * m];
    }

    __shared__ float sh_h[2][HID];
    __shared__ float red[8];
    float c_state = 0.0f;

    for (int t = 0; t < SEQ; t++) {
        const unsigned tg = (unsigned)t;
        float* shb = sh_h[t & 1];

        // xg prefetch: warp-uniform addresses -> LDG broadcast; issued
        // before the poll so latency hides behind the spin.
        const float* xp = g_xg + (size_t)t * GATES + unit;
        float xg0 = __ldg(xp);
        float xg1 = __ldg(xp + 512);
        float xg2 = __ldg(xp + 1024);
        float xg3 = __ldg(xp + 1536);

        // Phase A: pipelined poll of 2 tagged words, stage values to smem.
        {
            const unsigned long long* gp =
                &g_hp[(t + NBUF - 1) & (NBUF - 1)][rep][tid * 2];
            bool d0 = false, d1 = false;
            unsigned long long w0, w1;
            do {
                // Batch of 4 independent samples per word (issue-pipelined).
                unsigned long long s00 = ldg_strong(gp);
                unsigned long long s10 = ldg_strong(gp + 1);
                unsigned long long s01 = ldg_strong(gp);
                unsigned long long s11 = ldg_strong(gp + 1);
                unsigned long long s02 = ldg_strong(gp);
                unsigned long long s12 = ldg_strong(gp + 1);
                unsigned long long s03 = ldg_strong(gp);
                unsigned long long s13 = ldg_strong(gp + 1);
                if (!d0) {
                    if      ((unsigned)(s00 >> 32) == tg) { w0 = s00; d0 = true; }
                    else if ((unsigned)(s01 >> 32) == tg) { w0 = s01; d0 = true; }
                    else if ((unsigned)(s02 >> 32) == tg) { w0 = s02; d0 = true; }
                    else if ((unsigned)(s03 >> 32) == tg) { w0 = s03; d0 = true; }
                }
                if (!d1) {
                    if      ((unsigned)(s10 >> 32) == tg) { w1 = s10; d1 = true; }
                    else if ((unsigned)(s11 >> 32) == tg) { w1 = s11; d1 = true; }
                    else if ((unsigned)(s12 >> 32) == tg) { w1 = s12; d1 = true; }
                    else if ((unsigned)(s13 >> 32) == tg) { w1 = s13; d1 = true; }
                }
            } while (!(d0 && d1));
            shb[tid * 2]     = __uint_as_float((unsigned)w0);
            shb[tid * 2 + 1] = __uint_as_float((unsigned)w1);
        }
        __syncthreads();

        // Phase B: 4 gate dots + full-butterfly reduce (all lanes get sums).
        float a0 = 0.f, a1 = 0.f, a2 = 0.f, a3 = 0.f;
        #pragma unroll
        for (int m = 0; m < 16; m++) {
            float h = shb[lane + 32 * m];
            a0 = fmaf(w[0][m], h, a0);
            a1 = fmaf(w[1][m], h, a1);
            a2 = fmaf(w[2][m], h, a2);
            a3 = fmaf(w[3][m], h, a3);
        }
        #pragma unroll
        for (int off = 16; off; off >>= 1) {
            a0 += __shfl_xor_sync(0xffffffffu, a0, off);
            a1 += __shfl_xor_sync(0xffffffffu, a1, off);
            a2 += __shfl_xor_sync(0xffffffffu, a2, off);
            a3 += __shfl_xor_sync(0xffffffffu, a3, off);
        }

        // All lanes redundantly compute gates (same inputs, deterministic).
        float gi = fsigm(a0 + xg0);
        float gf = fsigm(a1 + xg1);
        float gg = ftanh(a2 + xg2);
        float go = fsigm(a3 + xg3);
        c_state = gf * c_state + gi * gg;
        float hn = go * ftanh(c_state);

        // Publish: lanes 0..NREP-1 store the replicas in parallel.
        unsigned long long pk =
            ((unsigned long long)(tg + 1u) << 32) |
            (unsigned long long)__float_as_uint(hn);
        if (lane < NREP)
            stg_strong(&g_hp[t & (NBUF - 1)][lane][unit], pk);
    }

    // ---- fused finalize: attention head + outputs ----
    {
        const unsigned tgF = (unsigned)SEQ;          // tag 1024 = h_1023
        float* shf = sh_h[0];                        // free: last read at t=1022
        const unsigned long long* gp =
            &g_hp[(SEQ + NBUF - 1) & (NBUF - 1)][rep][tid * 2];
        unsigned long long p0 = ldg_strong(gp);
        unsigned long long p1 = ldg_strong(gp + 1);
        while ((unsigned)(p0 >> 32) != tgF) p0 = ldg_strong(gp);
        while ((unsigned)(p1 >> 32) != tgF) p1 = ldg_strong(gp + 1);
        shf[tid * 2]     = __uint_as_float((unsigned)p0);
        shf[tid * 2 + 1] = __uint_as_float((unsigned)p1);
        __syncthreads();

        const int o = blockIdx.x;                    // output unit == CTA id
        float s = fmaf(shf[tid * 2],     attn_w[o * HID + tid * 2],
                  shf[tid * 2 + 1] * attn_w[o * HID + tid * 2 + 1]);
        #pragma unroll
        for (int off = 16; off; off >>= 1)
            s += __shfl_xor_sync(0xffffffffu, s, off);
        if (lane == 0) red[warp] = s;
        __syncthreads();
        if (tid == 0) {
            float tot = 0.f;
            #pragma unroll
            for (int i = 0; i < 8; i++) tot += red[i];
            red[0] = 1.0f / (1.0f + expf(-(tot + attn_b[o])));
        }
        __syncthreads();
        float a = red[0];
        #pragma unroll
        for (int p = tid; p < 1024; p += 256)
            out[o * 1024 + p] = a;                   // x_attention broadcast
        if (o == 0)
            for (int k = tid; k < HID; k += 256)
                out[65536 + k] = shf[k];             // x_instr_rep
    }
}

// ---------------- launch -------------------------------------------------
extern "C" void kernel_launch(void* const* d_in, const int* in_sizes, int n_in,
                              void* d_out, int out_size)
{
    const int*   tok    = (const int*)  d_in[0];
    const float* emb    = (const float*)d_in[1];
    const float* w_ih   = (const float*)d_in[2];
    const float* w_hh   = (const float*)d_in[3];
    const float* b_ih   = (const float*)d_in[4];
    const float* b_hh   = (const float*)d_in[5];
    const float* attn_w = (const float*)d_in[6];
    const float* attn_b = (const float*)d_in[7];
    float* out = (float*)d_out;

    dim3 gg(GATES / 64, SEQ / 64);           // 32 x 16 blocks
    xgates_gemm<<<gg, 256>>>(tok, emb, w_ih, b_ih, b_hh);
    lstm_scan<<<G_CTAS, 256>>>(w_hh, attn_w, attn_b, out);
}